// round 6
// baseline (speedup 1.0000x reference)
#include <cuda_runtime.h>

#define N 512
#define TPB 128            // threads per block; each owns 4 consecutive columns
#define NWARPS (TPB / 32)  // 4

// Closed form for the Givens-rotation chain (rotations on columns (i,i+1),
// i = N-2 .. 0, theta index == i):
//   U[r][j]   = 0                                        for j > r+1
//   U[r][r+1] = s_r
//   U[r][j]   = c_r * c_{j-1} * prod_{m=j}^{r-1} (-s_m)  for j <= r   (c_{N-1}:=1)
//
// Block b computes rows r0..r0+3 (r0 = 4b). Thread t owns columns 4t..4t+3.
// Needs T[j] = prod_{m=j}^{r0-1} (-s_m); mask (j < r0) is uniform per thread
// (cols < r0  <=>  t < b). Scan: 3 local muls -> 5-step warp shuffle suffix
// scan -> 4 warp totals via one broadcast LDS.128. One __syncthreads.
//
// IMPORTANT: x_k advances by -s_r only once column k has activated (jj <= r),
// matching the sequential recurrence (this was the R5 bug).
__global__ __launch_bounds__(TPB) void unitary_closed_form_kernel(
    const float* __restrict__ thetas,  // K = N-1 = 511 angles
    float* __restrict__ out)           // N x N row-major fp32
{
    __shared__ __align__(16) float sh_s[N];
    __shared__ __align__(16) float sh_c[N];
    __shared__ __align__(16) float shW[NWARPS];

    const int t    = threadIdx.x;
    const int lane = t & 31;
    const int w    = t >> 5;
    const int b    = blockIdx.x;
    const int r0   = b * 4;
    const int j0   = t * 4;

    // sincos of this thread's 4 thetas (clamped load; fix col N-1).
    float s[4], c[4];
    #pragma unroll
    for (int k = 0; k < 4; ++k) {
        int jj = j0 + k;
        __sincosf(__ldg(thetas + ((jj < N - 1) ? jj : (N - 2))), &s[k], &c[k]);
    }
    if (t == TPB - 1) { s[3] = 0.0f; c[3] = 1.0f; }   // column N-1

    reinterpret_cast<float4*>(sh_s)[t] = make_float4(s[0], s[1], s[2], s[3]);
    reinterpret_cast<float4*>(sh_c)[t] = make_float4(c[0], c[1], c[2], c[3]);

    // a_k = -s_k if this thread's columns are < r0 (t < b), else 1.
    const bool on = (t < b);
    float a0 = on ? -s[0] : 1.0f;
    float a1 = on ? -s[1] : 1.0f;
    float a2 = on ? -s[2] : 1.0f;
    float a3 = on ? -s[3] : 1.0f;

    // Local suffix products u_k = prod_{m=k}^{3} a_m.
    float u3 = a3;
    float u2 = a2 * a3;
    float u1 = a1 * u2;
    float u0 = a0 * u1;   // thread total L

    // Warp suffix-product scan of thread totals: P = prod_{l=lane}^{31} L_l.
    float P = u0;
    #pragma unroll
    for (int off = 1; off < 32; off <<= 1) {
        float v = __shfl_down_sync(0xffffffffu, P, off);
        if (lane + off < 32) P *= v;
    }
    if (lane == 0) shW[w] = P;   // full-warp product

    __syncthreads();             // covers sh_s, sh_c, shW

    // Exclusive-beyond-thread term:
    //   within warp: lanes lane+1..31 -> shfl_down(P,1), lane 31 -> 1
    //   beyond warp: prod of shW[w'] for w' > w (one LDS.128 broadcast)
    float Pe = __shfl_down_sync(0xffffffffu, P, 1);
    if (lane == 31) Pe = 1.0f;
    const float4 q = reinterpret_cast<const float4*>(shW)[0];
    float e = 1.0f;
    if (w < 1) e *= q.y;
    if (w < 2) e *= q.z;
    if (w < 3) e *= q.w;
    const float E = Pe * e;

    // x_k = c_{j-1} * T_k,  T_k = u_k * E  (= prod_{m=j}^{r0-1}(-s_m)).
    const float cm1 = (t > 0) ? sh_c[j0 - 1] : 1.0f;
    float xv[4];
    xv[0] = cm1  * (u0 * E);
    xv[1] = c[0] * (u1 * E);
    xv[2] = c[1] * (u2 * E);
    xv[3] = c[2] * (u3 * E);

    // Row constants for rows r0..r0+3 (one LDS.128 broadcast each; r0 = 4b).
    const float4 cr4 = reinterpret_cast<const float4*>(sh_c)[b];
    const float4 sr4 = reinterpret_cast<const float4*>(sh_s)[b];
    const float crk[4] = {cr4.x, cr4.y, cr4.z, cr4.w};
    const float srk[4] = {sr4.x, sr4.y, sr4.z, sr4.w};

    float4* orow = reinterpret_cast<float4*>(out + (size_t)r0 * N) + t;
    #pragma unroll
    for (int rr = 0; rr < 4; ++rr) {
        const int r = r0 + rr;
        float v[4];
        #pragma unroll
        for (int k = 0; k < 4; ++k) {
            const int jj = j0 + k;
            float val;
            if (jj <= r) {
                val = crk[rr] * xv[k];   // c_{N-1} == 1 handles r = N-1
                xv[k] *= -srk[rr];       // advance ONLY once activated
            } else if (jj == r + 1) {
                val = srk[rr];           // superdiagonal: s_r
            } else {
                val = 0.0f;
            }
            v[k] = val;
        }
        *orow = make_float4(v[0], v[1], v[2], v[3]);   // coalesced STG.128
        orow += N / 4;
    }
}

extern "C" void kernel_launch(void* const* d_in, const int* in_sizes, int n_in,
                              void* d_out, int out_size) {
    (void)in_sizes; (void)n_in; (void)out_size;
    const float* thetas = (const float*)d_in[0];
    float* out = (float*)d_out;
    unitary_closed_form_kernel<<<N / 4, TPB>>>(thetas, out);
}

// round 7
// speedup vs baseline: 1.0288x; 1.0288x over previous
#include <cuda_runtime.h>

#define N 512
#define TPB 128            // threads per block; each owns 4 consecutive columns
#define NWARPS (TPB / 32)  // 4

// Closed form for the Givens-rotation chain (rotations on columns (i,i+1),
// i = N-2 .. 0, theta index == i):
//   U[r][j]   = 0                                        for j > r+1
//   U[r][r+1] = s_r
//   U[r][j]   = c_r * c_{j-1} * prod_{m=j}^{r-1} (-s_m)  for j <= r   (c_{N-1}:=1)
//
// Block b: rows r0..r0+3 (r0 = 4b). Thread t: columns 4t..4t+3.
// Latency-skeleton-optimized version:
//   - smem is ONLY the 4 warp totals (16 B); row constants and the left
//     neighbor cosine are recomputed redundantly (uniform/predicated LDG +
//     MUFU sincos) so nothing but shW crosses the one __syncthreads.
//   - threads t > b+1 (all-zero outputs) store their 16 zeros immediately,
//     before the scan, overlapping the store traffic with the latency chain.
__global__ __launch_bounds__(TPB) void unitary_closed_form_kernel(
    const float* __restrict__ thetas,  // K = N-1 = 511 angles
    float* __restrict__ out)           // N x N row-major fp32
{
    __shared__ __align__(16) float shW[NWARPS];

    const int t    = threadIdx.x;
    const int lane = t & 31;
    const int w    = t >> 5;
    const int b    = blockIdx.x;
    const int r0   = b * 4;
    const int j0   = t * 4;

    float4* orow = reinterpret_cast<float4*>(out + (size_t)r0 * N) + t;

    // Early zero stores: columns >= r0 + 5 are all zero for every row of this
    // block; that's exactly threads t > b+1.
    const bool far = (t > b + 1);
    if (far) {
        const float4 z = make_float4(0.0f, 0.0f, 0.0f, 0.0f);
        float4* o = orow;
        #pragma unroll
        for (int rr = 0; rr < 4; ++rr) { *o = z; o += N / 4; }
    }

    // Own sincos (scan input + c[0..2] for x init). Clamped scalar loads.
    float s[4], c[4];
    #pragma unroll
    for (int k = 0; k < 4; ++k) {
        const int jj = j0 + k;
        __sincosf(__ldg(thetas + ((jj < N - 1) ? jj : (N - 2))), &s[k], &c[k]);
    }
    if (t == TPB - 1) { s[3] = 0.0f; c[3] = 1.0f; }   // column N-1

    // Row constants c_r, s_r for r = r0..r0+3: uniform, recomputed per thread
    // (independent of the scan -> overlaps it).
    float srk[4], crk[4];
    #pragma unroll
    for (int kk = 0; kk < 4; ++kk) {
        const int idx = r0 + kk;
        __sincosf(__ldg(thetas + ((idx < N - 1) ? idx : (N - 2))),
                  &srk[kk], &crk[kk]);
    }
    if (b == N / 4 - 1) { srk[3] = 0.0f; crk[3] = 1.0f; }   // row N-1

    // Left-neighbor cosine c_{j0-1}: shuffle from thread t-1 within the warp;
    // lane-0 threads (t = 32,64,96) recompute it directly; t = 0 uses 1.
    float cprev = __shfl_up_sync(0xffffffffu, c[3], 1);
    if (lane == 0) {
        cprev = 1.0f;
        if (t > 0) {
            float ss, cc;
            __sincosf(__ldg(thetas + (j0 - 1)), &ss, &cc);
            cprev = cc;
        }
    }

    // a_k = -s_k if this thread's columns are < r0 (t < b), else 1.
    const bool on = (t < b);
    const float a0 = on ? -s[0] : 1.0f;
    const float a1 = on ? -s[1] : 1.0f;
    const float a2 = on ? -s[2] : 1.0f;
    const float a3 = on ? -s[3] : 1.0f;

    // Local suffix products u_k = prod_{m=k}^{3} a_m.
    const float u3 = a3;
    const float u2 = a2 * a3;
    const float u1 = a1 * u2;
    const float u0 = a0 * u1;   // thread total

    // Warp suffix-product scan of thread totals: P = prod_{l=lane}^{31} L_l.
    float P = u0;
    #pragma unroll
    for (int off = 1; off < 32; off <<= 1) {
        float v = __shfl_down_sync(0xffffffffu, P, off);
        if (lane + off < 32) P *= v;
    }
    if (lane == 0) shW[w] = P;   // full-warp product

    __syncthreads();             // covers shW only

    // Exclusive-beyond-thread term:
    //   within warp: shfl_down(P,1), lane 31 -> 1
    //   beyond warp: prod of shW[w'] for w' > w (one broadcast LDS.128)
    float Pe = __shfl_down_sync(0xffffffffu, P, 1);
    if (lane == 31) Pe = 1.0f;
    const float4 q = reinterpret_cast<const float4*>(shW)[0];
    float e = 1.0f;
    if (w < 1) e *= q.y;
    if (w < 2) e *= q.z;
    if (w < 3) e *= q.w;
    const float E = Pe * e;

    if (!far) {
        // x_k = c_{j-1} * prod_{m=j}^{r0-1}(-s_m)
        float xv[4];
        xv[0] = cprev * (u0 * E);
        xv[1] = c[0]  * (u1 * E);
        xv[2] = c[1]  * (u2 * E);
        xv[3] = c[2]  * (u3 * E);

        float4* o = orow;
        #pragma unroll
        for (int rr = 0; rr < 4; ++rr) {
            const int r = r0 + rr;
            float v[4];
            #pragma unroll
            for (int k = 0; k < 4; ++k) {
                const int jj = j0 + k;
                float val;
                if (jj <= r) {
                    val = crk[rr] * xv[k];   // c_{N-1} == 1 handles r = N-1
                    xv[k] *= -srk[rr];       // advance ONLY once activated
                } else if (jj == r + 1) {
                    val = srk[rr];           // superdiagonal: s_r
                } else {
                    val = 0.0f;
                }
                v[k] = val;
            }
            *o = make_float4(v[0], v[1], v[2], v[3]);   // coalesced STG.128
            o += N / 4;
        }
    }
}

extern "C" void kernel_launch(void* const* d_in, const int* in_sizes, int n_in,
                              void* d_out, int out_size) {
    (void)in_sizes; (void)n_in; (void)out_size;
    const float* thetas = (const float*)d_in[0];
    float* out = (float*)d_out;
    unitary_closed_form_kernel<<<N / 4, TPB>>>(thetas, out);
}

// round 8
// speedup vs baseline: 1.0338x; 1.0048x over previous
#include <cuda_runtime.h>

#define N 512
#define TPB 256            // 2 row-groups x 128 column-threads
#define ROWS_PER_BLOCK 8
#define GRID (N / ROWS_PER_BLOCK)   // 64

// Closed form for the Givens-rotation chain (rotations on columns (i,i+1),
// i = N-2 .. 0, theta index == i):
//   U[r][j]   = 0                                        for j > r+1
//   U[r][r+1] = s_r
//   U[r][j]   = c_r * c_{j-1} * prod_{m=j}^{r-1} (-s_m)  for j <= r   (c_{N-1}:=1)
//
// Block b computes rows 8b..8b+7 as two independent 4-row groups:
//   group g (warps 4g..4g+3): rows r0 = 8b+4g .. r0+3
// Column-thread ct (= tid & 127) owns columns 4ct..4ct+3.
// Each group runs its own suffix-product scan (mask: ct < 2b+g, thread-
// uniform) + 4-warp combine via one broadcast LDS.128. One __syncthreads.
__global__ __launch_bounds__(TPB) void unitary_closed_form_kernel(
    const float* __restrict__ thetas,  // K = N-1 = 511 angles
    float* __restrict__ out)           // N x N row-major fp32
{
    __shared__ __align__(16) float sh_s[N];
    __shared__ __align__(16) float sh_c[N];
    __shared__ __align__(16) float shW[8];   // 4 warp totals per group

    const int t    = threadIdx.x;
    const int ct   = t & 127;          // column thread
    const int g    = t >> 7;           // row group 0/1
    const int lane = t & 31;
    const int gw   = t >> 5;           // warp id in block (0..7)
    const int wg   = gw & 3;           // warp id within group (0..3)
    const int b    = blockIdx.x;
    const int r0   = b * ROWS_PER_BLOCK + g * 4;
    const int j0   = ct * 4;

    // sincos of this thread's 4 columns (both groups compute the same values
    // for their ct — redundant but fully parallel). Clamped load; fix col N-1.
    float s[4], c[4];
    #pragma unroll
    for (int k = 0; k < 4; ++k) {
        const int jj = j0 + k;
        __sincosf(__ldg(thetas + ((jj < N - 1) ? jj : (N - 2))), &s[k], &c[k]);
    }
    if (ct == 127) { s[3] = 0.0f; c[3] = 1.0f; }   // column N-1

    if (g == 0) {   // one copy into the shared tables
        reinterpret_cast<float4*>(sh_s)[ct] = make_float4(s[0], s[1], s[2], s[3]);
        reinterpret_cast<float4*>(sh_c)[ct] = make_float4(c[0], c[1], c[2], c[3]);
    }

    // Scan input: a_k = -s_k iff all 4 columns < r0  (ct < 2b + g).
    const bool on = (ct < 2 * b + g);
    const float a0 = on ? -s[0] : 1.0f;
    const float a1 = on ? -s[1] : 1.0f;
    const float a2 = on ? -s[2] : 1.0f;
    const float a3 = on ? -s[3] : 1.0f;

    // Local suffix products u_k = prod_{m=k}^{3} a_m.
    const float u3 = a3;
    const float u2 = a2 * a3;
    const float u1 = a1 * u2;
    const float u0 = a0 * u1;   // thread total

    // Warp suffix-product scan of thread totals: P = prod_{l=lane}^{31} L_l.
    float P = u0;
    #pragma unroll
    for (int off = 1; off < 32; off <<= 1) {
        float v = __shfl_down_sync(0xffffffffu, P, off);
        if (lane + off < 32) P *= v;
    }
    if (lane == 0) shW[gw] = P;   // full-warp product

    __syncthreads();              // covers sh_s, sh_c, shW

    // Exclusive-beyond-thread term for this group:
    //   within warp: shfl_down(P,1), lane 31 -> 1
    //   beyond warp (within group): prod of shW[4g + w'] for w' > wg
    float Pe = __shfl_down_sync(0xffffffffu, P, 1);
    if (lane == 31) Pe = 1.0f;
    const float4 q = reinterpret_cast<const float4*>(shW)[g];
    float e = 1.0f;
    if (wg < 1) e *= q.y;
    if (wg < 2) e *= q.z;
    if (wg < 3) e *= q.w;
    const float E = Pe * e;

    // x_k = c_{j-1} * prod_{m=j}^{r0-1}(-s_m).
    const float cm1 = (ct > 0) ? sh_c[j0 - 1] : 1.0f;
    float xv[4];
    xv[0] = cm1  * (u0 * E);
    xv[1] = c[0] * (u1 * E);
    xv[2] = c[1] * (u2 * E);
    xv[3] = c[2] * (u3 * E);

    // Row constants for rows r0..r0+3: one broadcast LDS.128 each.
    const float4 cr4 = reinterpret_cast<const float4*>(sh_c)[2 * b + g];
    const float4 sr4 = reinterpret_cast<const float4*>(sh_s)[2 * b + g];
    const float crk[4] = {cr4.x, cr4.y, cr4.z, cr4.w};
    const float srk[4] = {sr4.x, sr4.y, sr4.z, sr4.w};

    float4* orow = reinterpret_cast<float4*>(out + (size_t)r0 * N) + ct;
    #pragma unroll
    for (int rr = 0; rr < 4; ++rr) {
        const int r = r0 + rr;
        float v[4];
        #pragma unroll
        for (int k = 0; k < 4; ++k) {
            const int jj = j0 + k;
            float val;
            if (jj <= r) {
                val = crk[rr] * xv[k];   // c_{N-1} == 1 handles r = N-1
                xv[k] *= -srk[rr];       // advance ONLY once activated
            } else if (jj == r + 1) {
                val = srk[rr];           // superdiagonal: s_r
            } else {
                val = 0.0f;
            }
            v[k] = val;
        }
        *orow = make_float4(v[0], v[1], v[2], v[3]);   // coalesced STG.128
        orow += N / 4;
    }
}

extern "C" void kernel_launch(void* const* d_in, const int* in_sizes, int n_in,
                              void* d_out, int out_size) {
    (void)in_sizes; (void)n_in; (void)out_size;
    const float* thetas = (const float*)d_in[0];
    float* out = (float*)d_out;
    unitary_closed_form_kernel<<<GRID, TPB>>>(thetas, out);
}